// round 8
// baseline (speedup 1.0000x reference)
#include <cuda_runtime.h>
#include <cuda_bf16.h>
#include <math.h>
#include <float.h>
#include <stdint.h>

#define BB 32
#define NN 1024
#define BN_TOT 32768
#define GXMAX 256

#define SWZ128(o) ((o) ^ (((o) >> 3) & 0x70))

__device__ __forceinline__ uint32_t smem_u32(const void* p) {
    uint32_t a;
    asm("{ .reg .u64 t; cvta.to.shared.u64 t, %1; cvt.u32.u64 %0, t; }"
        : "=r"(a) : "l"(p));
    return a;
}
__device__ __forceinline__ uint32_t pack_bf2(float lo, float hi) {
    uint32_t r;
    asm("cvt.rn.bf16x2.f32 %0, %1, %2;" : "=r"(r) : "f"(hi), "f"(lo));
    return r;
}
__device__ __forceinline__ void ldm_x4(uint32_t* r, uint32_t addr) {
    asm volatile("ldmatrix.sync.aligned.m8n8.x4.shared.b16 {%0,%1,%2,%3}, [%4];"
                 : "=r"(r[0]), "=r"(r[1]), "=r"(r[2]), "=r"(r[3]) : "r"(addr));
}
__device__ __forceinline__ void mma16816(float* d, const uint32_t* a, const uint32_t* b) {
    asm volatile(
        "mma.sync.aligned.m16n8k16.row.col.f32.bf16.bf16.f32 "
        "{%0,%1,%2,%3}, {%4,%5,%6,%7}, {%8,%9}, {%0,%1,%2,%3};"
        : "+f"(d[0]), "+f"(d[1]), "+f"(d[2]), "+f"(d[3])
        : "r"(a[0]), "r"(a[1]), "r"(a[2]), "r"(a[3]), "r"(b[0]), "r"(b[1]));
}
__device__ __forceinline__ void cp16(uint32_t dst, const void* src) {
    asm volatile("cp.async.cg.shared.global [%0], [%1], 16;" :: "r"(dst), "l"(src));
}
__device__ __forceinline__ void cp_commit() {
    asm volatile("cp.async.commit_group;" ::: "memory");
}
__device__ __forceinline__ void cp_wait0() {
    asm volatile("cp.async.wait_group 0;" ::: "memory");
}

// ===================== scratch =====================
static constexpr size_t CH = (size_t)BN_TOT;
static constexpr size_t OFF_H1 = 0;
static constexpr size_t OFF_H2 = OFF_H1 + 64 * CH;
static constexpr size_t OFF_H3 = OFF_H2 + 64 * CH;
static constexpr size_t OFF_H4 = OFF_H3 + 64 * CH;
static constexpr size_t OFF_H6 = OFF_H4 + 128 * CH;
static constexpr size_t OFF_H7 = OFF_H6 + 512 * CH;
static constexpr size_t OFF_H8 = OFF_H7 + 256 * CH;
static constexpr size_t OFF_H9 = OFF_H8 + 128 * CH;
static constexpr size_t OFF_MEAN = OFF_H9 + 128 * CH;
static constexpr size_t OFF_RSTD = OFF_MEAN + 10 * 1024;
static constexpr size_t OFF_B6   = OFF_RSTD + 10 * 1024;
static constexpr size_t OFF_CB   = OFF_B6 + (size_t)BB * 512;   // 4096 const biases
static constexpr size_t OFF_PS   = OFF_CB + 4096;
static constexpr size_t OFF_PQ   = OFF_PS + 1024 * (size_t)GXMAX;
static constexpr size_t OFF_PM   = OFF_PQ + 1024 * (size_t)GXMAX;
static constexpr size_t TOTAL_F  = OFF_PM + 1024 * (size_t)GXMAX;

__device__ float g_buf[TOTAL_F];
__device__ int g_cnt[10];

static constexpr size_t WTOT = 1161216;
__device__ __nv_bfloat16 g_whi[WTOT];
__device__ __nv_bfloat16 g_wlo[WTOT];

// ===================== layer table =====================
struct LayerP { int cin, cout, kp3, rows; unsigned woff; unsigned cboff; };
__constant__ LayerP c_L[10] = {
    {  2,   64,   48,  128,       0,    0},
    { 64,   64,  192,  128,    6144,  128},
    { 64,   64,  192,  128,   30720,  256},
    { 64,  128,  192,  128,   55296,  384},
    {128, 1024,  384, 1024,   79872,  512},
    { 64,  512,  192,  512,  473088, 1536},
    {512,  256, 1536,  256,  571392, 2048},
    {256,  128,  768,  128,  964608, 2304},
    {128,  128,  384,  128, 1062912, 2432},
    {128,    3,  384,  128, 1112064, 2560},
};
struct WPtrs { const float* p[10]; };

// ===================== weight convert: basis [t, t^2, t^3] ==============
// k in chunk of 48: elems 0..31 = pairs (wt1,wt2) of 16 channels; 32..47 = wt3.
__global__ __launch_bounds__(256) void wcvt_all(
    WPtrs wp, __nv_bfloat16* __restrict__ hi, __nv_bfloat16* __restrict__ lo)
{
    const LayerP L = c_L[blockIdx.y];
    int idx = blockIdx.x * 256 + threadIdx.x;
    if (idx >= L.rows * L.kp3) return;
    int r = idx / L.kp3, k = idx - r * L.kp3;
    int chunk = k / 48, rem = k - chunk * 48;
    int i, mode;
    if (rem < 32) { i = chunk * 16 + (rem >> 1); mode = rem & 1; }
    else          { i = chunk * 16 + (rem - 32); mode = 2; }
    float w = 0.0f;
    if (r < L.cout && i < L.cin) {
        const float* W = wp.p[blockIdx.y] + ((size_t)i * L.cout + r) * 4;
        if (mode == 0)      w = 2.0f * W[1] - 3.0f * W[3];
        else if (mode == 1) w = 3.75f * W[2];
        else                w = 7.0f * W[3];
    }
    __nv_bfloat16 h = __float2bfloat16(w);
    hi[L.woff + idx] = h;
    lo[L.woff + idx] = __float2bfloat16(w - __bfloat162float(h));
}

// ===================== constant bias: cb[o] = sum_i (W0 - 0.75 W2) ==========
__global__ __launch_bounds__(256) void cbias_all(WPtrs wp, float* __restrict__ cb)
{
    const LayerP L = c_L[blockIdx.y];
    int r = blockIdx.x * 256 + threadIdx.x;
    if (r >= L.rows) return;
    float s = 0.0f;
    if (r < L.cout) {
        const float* W = wp.p[blockIdx.y];
        for (int i = 0; i < L.cin; i++) {
            const float* q = W + ((size_t)i * L.cout + r) * 4;
            s += q[0] - 0.75f * q[2];
        }
    }
    cb[L.cboff + r] = s;
}

// ===================== fused featurize + split-bf16 HMMA GEMM ==============
// 512 threads = 16 warps (NWM x NWN), warp tile 64x32, K-chunk 48 (16 ch).
// SMEM rows padded to 128B; 2 stages of (M+NT)*256 bytes.
template <int NWM, int NWN, int NT>
__global__ __launch_bounds__(512) void kan_mma(
    const float* __restrict__ Hin, const float* __restrict__ mean,
    const float* __restrict__ rstd,
    const __nv_bfloat16* __restrict__ Whi, const __nv_bfloat16* __restrict__ Wlo,
    const float* __restrict__ cb, const float* __restrict__ bbias,
    float* __restrict__ out,
    float* __restrict__ psum, float* __restrict__ pq, float* __restrict__ pmax,
    float* __restrict__ outMean, float* __restrict__ outRstd,
    int Cin, int Cout, int Kp3, int nChunks,
    int writeMode /*0 normal,1 final,2 none*/, int doStats, int doMax,
    int inBatched, int layerId)
{
    constexpr int M = 64 * NWM;
    constexpr int S_WH = 0;
    constexpr int S_WL = M * 128;
    constexpr int S_FH = 2 * M * 128;
    constexpr int S_FL = 2 * M * 128 + NT * 128;
    constexpr int S_STG = (M + NT) * 256;
    constexpr int NJ = NT / 32;

    extern __shared__ __align__(1024) char dsm[];
    __shared__ int sLast;
    const uint32_t sb = smem_u32(dsm);
    const int tid = threadIdx.x;
    const int wid = tid >> 5;
    const int lane = tid & 31;
    const int warpM = wid / NWN;
    const int warpN = wid % NWN;
    const int pBase = blockIdx.x * NT;
    const int oBase = blockIdx.y * M;
    const int bIdx = pBase >> 10;
    const bool hasBN = (mean != nullptr);

    float acc[4][4][4];
#pragma unroll
    for (int mt = 0; mt < 4; mt++)
#pragma unroll
        for (int nt = 0; nt < 4; nt++)
#pragma unroll
            for (int e = 0; e < 4; e++) acc[mt][nt][e] = 0.0f;

    const int icl = tid >> 5;       // producer channel (0..15)
    const int pl  = tid & 31;       // producer point sub-index

    auto stageW = [&](int kc, int sOff) {
        for (int idx = tid; idx < M * 6; idx += 512) {
            int row = idx / 6, c = idx - row * 6;
            const __nv_bfloat16* gh = Whi + (size_t)(oBase + row) * Kp3 + kc * 48 + c * 8;
            const __nv_bfloat16* gl = Wlo + (size_t)(oBase + row) * Kp3 + kc * 48 + c * 8;
            uint32_t off = SWZ128(row * 128 + c * 16);
            cp16(sb + sOff + S_WH + off, gh);
            cp16(sb + sOff + S_WL + off, gl);
        }
    };
    auto featStore = [&](int kc, int sOff) {
        const int ch = kc * 16 + icl;
        const bool valid = ch < Cin;
        float mn = 0.f, rs = 1.f;
        if (hasBN && valid) { mn = mean[ch]; rs = rstd[ch]; }
        const float* hrow;
        if (inBatched)
            hrow = Hin + ((size_t)bIdx * Cin + (valid ? ch : 0)) * NN + (pBase & (NN - 1));
        else
            hrow = Hin + (size_t)(valid ? ch : 0) * BN_TOT + pBase;
        float av[NJ];
#pragma unroll
        for (int j = 0; j < NJ; j++)
            av[j] = valid ? hrow[pl + 32 * j] : 0.0f;
#pragma unroll
        for (int j = 0; j < NJ; j++) {
            const int p = pl + 32 * j;
            float v = hasBN ? (av[j] - mn) * rs : av[j];
            float t = tanhf(v);
            float f2 = t * t;
            float f3 = f2 * t;
            uint32_t h12 = pack_bf2(t, f2);
            float ht  = __uint_as_float(h12 << 16);
            float hf2 = __uint_as_float(h12 & 0xFFFF0000u);
            uint32_t l12 = pack_bf2(t - ht, f2 - hf2);
            uint32_t h3p = pack_bf2(f3, 0.0f);
            uint16_t h3 = (uint16_t)h3p;
            float hf3 = __uint_as_float((uint32_t)h3 << 16);
            uint16_t l3 = (uint16_t)pack_bf2(f3 - hf3, 0.0f);
            uint32_t oPair = SWZ128(p * 128 + icl * 4);
            uint32_t oCube = SWZ128(p * 128 + 64 + icl * 2);
            *(uint32_t*)(dsm + sOff + S_FH + oPair) = h12;
            *(uint32_t*)(dsm + sOff + S_FL + oPair) = l12;
            *(uint16_t*)(dsm + sOff + S_FH + oCube) = h3;
            *(uint16_t*)(dsm + sOff + S_FL + oCube) = l3;
        }
    };
    auto doMMA = [&](int sOff) {
#pragma unroll
        for (int ks = 0; ks < 3; ks++) {
            uint32_t ah[4][4], al[4][4];
#pragma unroll
            for (int mt = 0; mt < 4; mt++) {
                int r = warpM * 64 + mt * 16 + (lane & 15);
                int cB = ks * 32 + (lane >> 4) * 16;
                uint32_t a = sb + sOff + SWZ128(r * 128 + cB);
                ldm_x4(ah[mt], a + S_WH);
                ldm_x4(al[mt], a + S_WL);
            }
#pragma unroll
            for (int ntp = 0; ntp < 2; ntp++) {
                uint32_t fh[4], fl[4];
                int rN = warpN * 32 + ntp * 16 + ((lane >> 4) << 3) + (lane & 7);
                int cB = ks * 32 + ((lane >> 3) & 1) * 16;
                uint32_t a = sb + sOff + SWZ128(rN * 128 + cB);
                ldm_x4(fh, a + S_FH);
                ldm_x4(fl, a + S_FL);
#pragma unroll
                for (int mt = 0; mt < 4; mt++)
#pragma unroll
                    for (int s = 0; s < 2; s++) {
                        int nt = 2 * ntp + s;
                        mma16816(acc[mt][nt], ah[mt], &fh[2 * s]);
                        mma16816(acc[mt][nt], al[mt], &fh[2 * s]);
                        mma16816(acc[mt][nt], ah[mt], &fl[2 * s]);
                    }
            }
        }
    };

    // ---- prologue ----
    stageW(0, 0); cp_commit();
    featStore(0, 0);
    cp_wait0();
    __syncthreads();

    // ---- pipelined main loop ----
    for (int kc = 0; kc < nChunks; kc++) {
        const int sOff = (kc & 1) ? S_STG : 0;
        const int nOff = (kc & 1) ? 0 : S_STG;
        const bool more = (kc + 1 < nChunks);
        if (more) {
            stageW(kc + 1, nOff); cp_commit();
        }
        doMMA(sOff);
        if (more) {
            featStore(kc + 1, nOff);
            cp_wait0();
        }
        __syncthreads();
    }

    // ---- epilogue: bias ----
#pragma unroll
    for (int mt = 0; mt < 4; mt++)
#pragma unroll
        for (int h = 0; h < 2; h++) {
            int o = oBase + warpM * 64 + mt * 16 + h * 8 + (lane >> 2);
            float bv = cb[o];
            if (bbias && o < Cout) bv += bbias[bIdx * Cout + o];
#pragma unroll
            for (int nt = 0; nt < 4; nt++) {
                acc[mt][nt][h * 2 + 0] += bv;
                acc[mt][nt][h * 2 + 1] += bv;
            }
        }

    if (writeMode == 0) {
#pragma unroll
        for (int mt = 0; mt < 4; mt++)
#pragma unroll
            for (int h = 0; h < 2; h++) {
                int o = oBase + warpM * 64 + mt * 16 + h * 8 + (lane >> 2);
                if (o < Cout) {
                    float* rowp = out + (size_t)o * BN_TOT + pBase;
#pragma unroll
                    for (int nt = 0; nt < 4; nt++) {
                        int p = warpN * 32 + nt * 8 + (lane & 3) * 2;
                        *(float2*)(rowp + p) =
                            make_float2(acc[mt][nt][h * 2], acc[mt][nt][h * 2 + 1]);
                    }
                }
            }
    } else if (writeMode == 1) {
#pragma unroll
        for (int mt = 0; mt < 4; mt++)
#pragma unroll
            for (int h = 0; h < 2; h++) {
                int o = oBase + warpM * 64 + mt * 16 + h * 8 + (lane >> 2);
                if (o < 3) {
                    float* rowp = out + ((size_t)bIdx * 3 + o) * NN + (pBase & (NN - 1));
#pragma unroll
                    for (int nt = 0; nt < 4; nt++) {
                        int p = warpN * 32 + nt * 8 + (lane & 3) * 2;
                        rowp[p]     = acc[mt][nt][h * 2];
                        rowp[p + 1] = acc[mt][nt][h * 2 + 1];
                    }
                }
            }
    }

    if (doStats) {
        float* red = (float*)dsm;
#pragma unroll
        for (int mt = 0; mt < 4; mt++)
#pragma unroll
            for (int h = 0; h < 2; h++) {
                float s = 0.f, q = 0.f, mx = -FLT_MAX;
#pragma unroll
                for (int nt = 0; nt < 4; nt++)
#pragma unroll
                    for (int e = 0; e < 2; e++) {
                        float v = acc[mt][nt][h * 2 + e];
                        s += v; q += v * v; mx = fmaxf(mx, v);
                    }
                s += __shfl_xor_sync(~0u, s, 1); s += __shfl_xor_sync(~0u, s, 2);
                q += __shfl_xor_sync(~0u, q, 1); q += __shfl_xor_sync(~0u, q, 2);
                mx = fmaxf(mx, __shfl_xor_sync(~0u, mx, 1));
                mx = fmaxf(mx, __shfl_xor_sync(~0u, mx, 2));
                if ((lane & 3) == 0) {
                    int row = warpM * 64 + mt * 16 + h * 8 + (lane >> 2);
                    red[warpN * M + row] = s;
                    red[NWN * M + warpN * M + row] = q;
                    if (doMax) red[2 * NWN * M + warpN * M + row] = mx;
                }
            }
        __syncthreads();
        if (tid < M) {
            float s = 0.f, q = 0.f, mx = -FLT_MAX;
#pragma unroll
            for (int wn = 0; wn < NWN; wn++) {
                s += red[wn * M + tid];
                q += red[NWN * M + wn * M + tid];
                if (doMax) mx = fmaxf(mx, red[2 * NWN * M + wn * M + tid]);
            }
            int o = oBase + tid;
            psum[(size_t)o * GXMAX + blockIdx.x] = s;
            pq[(size_t)o * GXMAX + blockIdx.x] = q;
            if (doMax) pmax[(size_t)o * GXMAX + blockIdx.x] = mx;
        }
        __syncthreads();
        // ---- last-CTA BN finalize ----
        if (tid == 0) {
            __threadfence();
            int n = atomicAdd(&g_cnt[layerId], 1);
            sLast = (n == (int)(gridDim.x * gridDim.y) - 1) ? 1 : 0;
        }
        __syncthreads();
        if (sLast) {
            __threadfence();
            const int gx = gridDim.x;
            for (int c = tid; c < Cout; c += 512) {
                float s = 0.f, q = 0.f;
                for (int j = 0; j < gx; j++) {
                    s += psum[(size_t)c * GXMAX + j];
                    q += pq[(size_t)c * GXMAX + j];
                }
                float m = s * (1.0f / BN_TOT);
                outMean[c] = m;
                outRstd[c] = rsqrtf(q * (1.0f / BN_TOT) - m * m + 1e-5f);
            }
            __threadfence();
            if (tid == 0) g_cnt[layerId] = 0;
        }
    }
}

// ============ gf (max over 8 tiles + BN) + bias6 fold, batch-blocked ========
__global__ __launch_bounds__(256) void gfbias6(
    const float* __restrict__ pm, const float* __restrict__ mean,
    const float* __restrict__ rstd, const float* __restrict__ W6,
    float* __restrict__ bias6)
{
    extern __shared__ float feat[];   // 4 * 4096 floats
    const int by = blockIdx.y;        // 8 groups of 4 batches
#pragma unroll
    for (int bb = 0; bb < 4; bb++) {
        int b = by * 4 + bb;
        for (int c = threadIdx.x; c < 1024; c += 256) {
            float mx = -FLT_MAX;
#pragma unroll
            for (int j = 0; j < 8; j++)
                mx = fmaxf(mx, pm[(size_t)c * GXMAX + b * 8 + j]);
            float g = (mx - mean[c]) * rstd[c];
            float t = tanhf(g);
            float q1 = 2.0f * t;
            float q2 = 3.75f * t * t - 0.75f;
            float q3 = 1.8666666666666667f * t * q2 - 0.8f * q1;
            feat[bb * 4096 + c * 4 + 0] = 1.0f;
            feat[bb * 4096 + c * 4 + 1] = q1;
            feat[bb * 4096 + c * 4 + 2] = q2;
            feat[bb * 4096 + c * 4 + 3] = q3;
        }
    }
    __syncthreads();
    const int o = blockIdx.x * 256 + threadIdx.x;
    float acc[4] = {0.f, 0.f, 0.f, 0.f};
    for (int c = 0; c < 1024; c++) {
        float4 w = *(const float4*)(W6 + ((size_t)(64 + c) * 512 + o) * 4);
#pragma unroll
        for (int bb = 0; bb < 4; bb++) {
            float4 f = *(const float4*)&feat[bb * 4096 + c * 4];
            acc[bb] += f.x * w.x + f.y * w.y + f.z * w.z + f.w * w.w;
        }
    }
#pragma unroll
    for (int bb = 0; bb < 4; bb++)
        bias6[(by * 4 + bb) * 512 + o] = acc[bb];
}

// ===================== host =====================
static const LayerP h_L[10] = {
    {  2,   64,   48,  128,       0,    0},
    { 64,   64,  192,  128,    6144,  128},
    { 64,   64,  192,  128,   30720,  256},
    { 64,  128,  192,  128,   55296,  384},
    {128, 1024,  384, 1024,   79872,  512},
    { 64,  512,  192,  512,  473088, 1536},
    {512,  256, 1536,  256,  571392, 2048},
    {256,  128,  768,  128,  964608, 2304},
    {128,  128,  384,  128, 1062912, 2432},
    {128,    3,  384,  128, 1112064, 2560},
};

static constexpr int SMEM_TILE = 196608;   // (256+128)*256 = (128+256)*256

extern "C" void kernel_launch(void* const* d_in, const int* in_sizes, int n_in,
                              void* d_out, int out_size)
{
    (void)in_sizes; (void)n_in; (void)out_size;
    const float* x = (const float*)d_in[0];
    WPtrs wp;
    for (int i = 0; i < 10; i++) wp.p[i] = (const float*)d_in[1 + i];

    float* buf = nullptr;
    cudaGetSymbolAddress((void**)&buf, g_buf);
    __nv_bfloat16* whi = nullptr;
    __nv_bfloat16* wlo = nullptr;
    cudaGetSymbolAddress((void**)&whi, g_whi);
    cudaGetSymbolAddress((void**)&wlo, g_wlo);

    float* h1 = buf + OFF_H1;
    float* h2 = buf + OFF_H2;
    float* h3 = buf + OFF_H3;
    float* h4 = buf + OFF_H4;
    float* h6 = buf + OFF_H6;
    float* h7 = buf + OFF_H7;
    float* h8 = buf + OFF_H8;
    float* h9 = buf + OFF_H9;
    float* meanB = buf + OFF_MEAN;
    float* rstdB = buf + OFF_RSTD;
    float* bias6 = buf + OFF_B6;
    float* cbB   = buf + OFF_CB;
    float* ps    = buf + OFF_PS;
    float* pqb   = buf + OFF_PQ;
    float* pm    = buf + OFF_PM;

    cudaFuncSetAttribute(kan_mma<4, 4, 128>,
                         cudaFuncAttributeMaxDynamicSharedMemorySize, SMEM_TILE);
    cudaFuncSetAttribute(kan_mma<2, 8, 256>,
                         cudaFuncAttributeMaxDynamicSharedMemorySize, SMEM_TILE);
    cudaFuncSetAttribute(gfbias6,
                         cudaFuncAttributeMaxDynamicSharedMemorySize, 65536);

    {
        dim3 g(1536, 10);
        wcvt_all<<<g, 256>>>(wp, whi, wlo);
    }
    {
        dim3 g(4, 10);
        cbias_all<<<g, 256>>>(wp, cbB);
    }

    auto M = [&](int s) { return meanB + s * 1024; };
    auto R = [&](int s) { return rstdB + s * 1024; };

    auto gbig = [&](int l, const float* Hin, const float* mn, const float* rs,
                    const float* bb, float* Hout, int wm, int st, int mx,
                    float* oM, float* oR) {
        dim3 grid(BN_TOT / 128, h_L[l].rows / 256, 1);
        kan_mma<4, 4, 128><<<grid, 512, SMEM_TILE>>>(Hin, mn, rs,
            whi + h_L[l].woff, wlo + h_L[l].woff, cbB + h_L[l].cboff, bb,
            Hout, ps, pqb, pm, oM, oR,
            h_L[l].cin, h_L[l].cout, h_L[l].kp3, h_L[l].kp3 / 48, wm, st, mx, 0, l);
    };
    auto gsm = [&](int l, const float* Hin, const float* mn, const float* rs,
                   const float* bb, float* Hout, int wm, int st, int mx, int ib,
                   float* oM, float* oR) {
        dim3 grid(BN_TOT / 256, h_L[l].rows / 128, 1);
        kan_mma<2, 8, 256><<<grid, 512, SMEM_TILE>>>(Hin, mn, rs,
            whi + h_L[l].woff, wlo + h_L[l].woff, cbB + h_L[l].cboff, bb,
            Hout, ps, pqb, pm, oM, oR,
            h_L[l].cin, h_L[l].cout, h_L[l].kp3, h_L[l].kp3 / 48, wm, st, mx, ib, l);
    };

    gsm(0, x, nullptr, nullptr, nullptr, h1, 0, 1, 0, 1, M(0), R(0));
    gsm(1, h1, M(0), R(0), nullptr, h2, 0, 1, 0, 0, M(1), R(1));
    gsm(2, h2, M(1), R(1), nullptr, h3, 0, 1, 0, 0, M(2), R(2));
    gsm(3, h3, M(2), R(2), nullptr, h4, 0, 1, 0, 0, M(3), R(3));
    gbig(4, h4, M(3), R(3), nullptr, nullptr, 2, 1, 1, M(4), R(4));

    {
        dim3 g(2, 8);
        gfbias6<<<g, 256, 65536>>>(pm, M(4), R(4), wp.p[5], bias6);
    }

    gbig(5, h2, M(1), R(1), bias6, h6, 0, 1, 0, M(5), R(5));
    gbig(6, h6, M(5), R(5), nullptr, h7, 0, 1, 0, M(6), R(6));
    gsm(7, h7, M(6), R(6), nullptr, h8, 0, 1, 0, 0, M(7), R(7));
    gsm(8, h8, M(7), R(7), nullptr, h9, 0, 1, 0, 0, M(8), R(8));
    gsm(9, h9, M(8), R(8), nullptr, (float*)d_out, 1, 0, 0, 0, nullptr, nullptr);
}

// round 9
// speedup vs baseline: 1.3931x; 1.3931x over previous
#include <cuda_runtime.h>
#include <cuda_bf16.h>
#include <math.h>
#include <float.h>
#include <stdint.h>

#define BB 32
#define NN 1024
#define BN_TOT 32768
#define GXMAX 256

#define SWZ128(o) ((o) ^ (((o) >> 3) & 0x70))

__device__ __forceinline__ uint32_t smem_u32(const void* p) {
    uint32_t a;
    asm("{ .reg .u64 t; cvta.to.shared.u64 t, %1; cvt.u32.u64 %0, t; }"
        : "=r"(a) : "l"(p));
    return a;
}
__device__ __forceinline__ uint32_t pack_bf2(float lo, float hi) {
    uint32_t r;
    asm("cvt.rn.bf16x2.f32 %0, %1, %2;" : "=r"(r) : "f"(hi), "f"(lo));
    return r;
}
// fast tanh: t = 1 - 2/(2^(2*log2e*v) + 1); exact at +-inf, err ~1e-6
__device__ __forceinline__ float tanh_fast(float v) {
    float e;
    asm("ex2.approx.f32 %0, %1;" : "=f"(e) : "f"(v * 2.8853900817779268f));
    float r;
    asm("rcp.approx.f32 %0, %1;" : "=f"(r) : "f"(e + 1.0f));
    return fmaf(-2.0f, r, 1.0f);
}
__device__ __forceinline__ void ldm_x4(uint32_t* r, uint32_t addr) {
    asm volatile("ldmatrix.sync.aligned.m8n8.x4.shared.b16 {%0,%1,%2,%3}, [%4];"
                 : "=r"(r[0]), "=r"(r[1]), "=r"(r[2]), "=r"(r[3]) : "r"(addr));
}
__device__ __forceinline__ void mma16816(float* d, const uint32_t* a, const uint32_t* b) {
    asm volatile(
        "mma.sync.aligned.m16n8k16.row.col.f32.bf16.bf16.f32 "
        "{%0,%1,%2,%3}, {%4,%5,%6,%7}, {%8,%9}, {%0,%1,%2,%3};"
        : "+f"(d[0]), "+f"(d[1]), "+f"(d[2]), "+f"(d[3])
        : "r"(a[0]), "r"(a[1]), "r"(a[2]), "r"(a[3]), "r"(b[0]), "r"(b[1]));
}
__device__ __forceinline__ void cp16(uint32_t dst, const void* src) {
    asm volatile("cp.async.cg.shared.global [%0], [%1], 16;" :: "r"(dst), "l"(src));
}
__device__ __forceinline__ void cp_commit() {
    asm volatile("cp.async.commit_group;" ::: "memory");
}
__device__ __forceinline__ void cp_wait0() {
    asm volatile("cp.async.wait_group 0;" ::: "memory");
}

// ===================== scratch =====================
static constexpr size_t CH = (size_t)BN_TOT;
static constexpr size_t OFF_H1 = 0;
static constexpr size_t OFF_H2 = OFF_H1 + 64 * CH;
static constexpr size_t OFF_H3 = OFF_H2 + 64 * CH;
static constexpr size_t OFF_H4 = OFF_H3 + 64 * CH;
static constexpr size_t OFF_H6 = OFF_H4 + 128 * CH;
static constexpr size_t OFF_H7 = OFF_H6 + 512 * CH;
static constexpr size_t OFF_H8 = OFF_H7 + 256 * CH;
static constexpr size_t OFF_H9 = OFF_H8 + 128 * CH;
static constexpr size_t OFF_MEAN = OFF_H9 + 128 * CH;
static constexpr size_t OFF_RSTD = OFF_MEAN + 10 * 1024;
static constexpr size_t OFF_B6   = OFF_RSTD + 10 * 1024;
static constexpr size_t OFF_PS   = OFF_B6 + (size_t)BB * 512;
static constexpr size_t OFF_PQ   = OFF_PS + 1024 * (size_t)GXMAX;
static constexpr size_t OFF_PM   = OFF_PQ + 1024 * (size_t)GXMAX;
static constexpr size_t TOTAL_F  = OFF_PM + 1024 * (size_t)GXMAX;

__device__ float g_buf[TOTAL_F];

static constexpr size_t WTOT = 1548288;
__device__ __nv_bfloat16 g_whi[WTOT];
__device__ __nv_bfloat16 g_wlo[WTOT];

// ===================== layer table =====================
struct LayerP { int cin, cout, kp, rows; unsigned woff; };
__constant__ LayerP c_L[10] = {
    {  2,   64,   64,  128,       0},
    { 64,   64,  256,  128,    8192},
    { 64,   64,  256,  128,   40960},
    { 64,  128,  256,  128,   73728},
    {128, 1024,  512, 1024,  106496},
    { 64,  512,  256,  512,  630784},
    {512,  256, 2048,  256,  761856},
    {256,  128, 1024,  128, 1286144},
    {128,  128,  512,  128, 1417216},
    {128,    3,  512,  128, 1482752},
};
struct WPtrs { const float* p[10]; };

// ===================== weight convert (all layers, one launch) ==============
__global__ __launch_bounds__(256) void wcvt_all(
    WPtrs wp, __nv_bfloat16* __restrict__ hi, __nv_bfloat16* __restrict__ lo)
{
    const LayerP L = c_L[blockIdx.y];
    int idx = blockIdx.x * 256 + threadIdx.x;
    if (idx >= L.rows * L.kp) return;
    int r = idx / L.kp, k = idx - r * L.kp;
    int i = k >> 2, d = k & 3;
    float w = 0.0f;
    if (r < L.cout && i < L.cin)
        w = wp.p[blockIdx.y][((size_t)i * L.cout + r) * 4 + d];
    __nv_bfloat16 h = __float2bfloat16(w);
    hi[L.woff + idx] = h;
    lo[L.woff + idx] = __float2bfloat16(w - __bfloat162float(h));
}

// ===================== fused featurize + split-bf16 HMMA GEMM ==============
// 512 threads = 16 warps (NWM x NWN), warp tile 64x32.
// CTA tile: M = 64*NWM outs x NT points. 2 smem stages of (M+NT)*256 bytes.
template <int NWM, int NWN, int NT>
__global__ __launch_bounds__(512) void kan_mma(
    const float* __restrict__ Hin, const float* __restrict__ mean,
    const float* __restrict__ rstd,
    const __nv_bfloat16* __restrict__ Whi, const __nv_bfloat16* __restrict__ Wlo,
    const float* __restrict__ bias, float* __restrict__ out,
    float* __restrict__ psum, float* __restrict__ pq, float* __restrict__ pmax,
    int Cin, int Cout, int Kp, int nChunks,
    int writeMode /*0 normal,1 final,2 none*/, int doStats, int doMax,
    int inBatched)
{
    constexpr int M = 64 * NWM;
    constexpr int S_WH = 0;
    constexpr int S_WL = M * 128;
    constexpr int S_FH = 2 * M * 128;
    constexpr int S_FL = 2 * M * 128 + NT * 128;
    constexpr int S_STG = (M + NT) * 256;
    constexpr int NJ = NT / 32;

    extern __shared__ __align__(1024) char dsm[];
    const uint32_t sb = smem_u32(dsm);
    const int tid = threadIdx.x;
    const int wid = tid >> 5;
    const int lane = tid & 31;
    const int warpM = wid / NWN;    // 0..NWM-1 : 64 out rows each
    const int warpN = wid % NWN;    // 0..NWN-1 : 32 points each
    const int pBase = blockIdx.x * NT;
    const int oBase = blockIdx.y * M;
    const int bIdx = pBase >> 10;
    const bool hasBN = (mean != nullptr);

    float acc[4][4][4];
#pragma unroll
    for (int mt = 0; mt < 4; mt++)
#pragma unroll
        for (int nt = 0; nt < 4; nt++)
#pragma unroll
            for (int e = 0; e < 4; e++) acc[mt][nt][e] = 0.0f;

    const int icl = tid >> 5;       // producer channel (0..15)
    const int pl  = tid & 31;       // producer point sub-index

    auto stageW = [&](int kc, int sOff) {
#pragma unroll
        for (int l = 0; l < M / 64; l++) {
            int idx = tid + l * 512;
            int row = idx >> 3, c16 = idx & 7;
            size_t g = (size_t)(oBase + row) * Kp + (size_t)kc * 64 + c16 * 8;
            uint32_t off = SWZ128(row * 128 + c16 * 16);
            cp16(sb + sOff + S_WH + off, Whi + g);
            cp16(sb + sOff + S_WL + off, Wlo + g);
        }
    };
    auto featStore = [&](int kc, int sOff) {
        const int ch = kc * 16 + icl;
        const bool valid = ch < Cin;
        float mn = 0.f, rs = 1.f;
        if (hasBN && valid) { mn = mean[ch]; rs = rstd[ch]; }
        const float* hrow;
        if (inBatched)
            hrow = Hin + ((size_t)bIdx * Cin + (valid ? ch : 0)) * NN + (pBase & (NN - 1));
        else
            hrow = Hin + (size_t)(valid ? ch : 0) * BN_TOT + pBase;
        float av[NJ];
#pragma unroll
        for (int j = 0; j < NJ; j++)
            av[j] = valid ? hrow[pl + 32 * j] : 0.0f;
#pragma unroll
        for (int j = 0; j < NJ; j++) {
            const int p = pl + 32 * j;
            float v = hasBN ? (av[j] - mn) * rs : av[j];
            float t = tanh_fast(v);
            float q1 = 2.0f * t;
            float q2 = 3.75f * t * t - 0.75f;
            float q3 = 1.8666666666666667f * t * q2 - 0.8f * q1;
            uint32_t w01 = pack_bf2(1.0f, q1);
            uint32_t w23 = pack_bf2(q2, q3);
            float h1f = __uint_as_float(w01 & 0xFFFF0000u);
            float h2f = __uint_as_float(w23 << 16);
            float h3f = __uint_as_float(w23 & 0xFFFF0000u);
            uint32_t l01 = pack_bf2(0.0f, q1 - h1f);
            uint32_t l23 = pack_bf2(q2 - h2f, q3 - h3f);
            int o0 = SWZ128(p * 128 + icl * 8);
            *(uint2*)(dsm + sOff + S_FH + o0) = make_uint2(w01, w23);
            *(uint2*)(dsm + sOff + S_FL + o0) = make_uint2(l01, l23);
        }
    };
    auto doMMA = [&](int sOff) {
#pragma unroll
        for (int ks = 0; ks < 4; ks++) {
            uint32_t ah[4][4], al[4][4];
#pragma unroll
            for (int mt = 0; mt < 4; mt++) {
                int r = warpM * 64 + mt * 16 + (lane & 15);
                int cB = ks * 32 + (lane >> 4) * 16;
                uint32_t a = sb + sOff + SWZ128(r * 128 + cB);
                ldm_x4(ah[mt], a + S_WH);
                ldm_x4(al[mt], a + S_WL);
            }
#pragma unroll
            for (int ntp = 0; ntp < 2; ntp++) {
                uint32_t fh[4], fl[4];
                int rN = warpN * 32 + ntp * 16 + ((lane >> 4) << 3) + (lane & 7);
                int cB = ks * 32 + ((lane >> 3) & 1) * 16;
                uint32_t a = sb + sOff + SWZ128(rN * 128 + cB);
                ldm_x4(fh, a + S_FH);
                ldm_x4(fl, a + S_FL);
#pragma unroll
                for (int mt = 0; mt < 4; mt++)
#pragma unroll
                    for (int s = 0; s < 2; s++) {
                        int nt = 2 * ntp + s;
                        mma16816(acc[mt][nt], ah[mt], &fh[2 * s]);
                        mma16816(acc[mt][nt], al[mt], &fh[2 * s]);
                        mma16816(acc[mt][nt], ah[mt], &fl[2 * s]);
                    }
            }
        }
    };

    // ---- prologue ----
    stageW(0, 0); cp_commit();
    featStore(0, 0);
    cp_wait0();
    __syncthreads();

    // ---- pipelined main loop ----
    for (int kc = 0; kc < nChunks; kc++) {
        const int sOff = (kc & 1) ? S_STG : 0;
        const int nOff = (kc & 1) ? 0 : S_STG;
        const bool more = (kc + 1 < nChunks);
        if (more) {
            stageW(kc + 1, nOff); cp_commit();
        }
        doMMA(sOff);
        if (more) {
            featStore(kc + 1, nOff);
            cp_wait0();
        }
        __syncthreads();
    }

    // ---- epilogue ----
#pragma unroll
    for (int mt = 0; mt < 4; mt++)
#pragma unroll
        for (int h = 0; h < 2; h++) {
            int o = oBase + warpM * 64 + mt * 16 + h * 8 + (lane >> 2);
            float bv = 0.f;
            if (bias && o < Cout) bv = bias[bIdx * Cout + o];
            if (bv != 0.f)
#pragma unroll
                for (int nt = 0; nt < 4; nt++) {
                    acc[mt][nt][h * 2 + 0] += bv;
                    acc[mt][nt][h * 2 + 1] += bv;
                }
        }

    if (writeMode == 0) {
#pragma unroll
        for (int mt = 0; mt < 4; mt++)
#pragma unroll
            for (int h = 0; h < 2; h++) {
                int o = oBase + warpM * 64 + mt * 16 + h * 8 + (lane >> 2);
                if (o < Cout) {
                    float* rowp = out + (size_t)o * BN_TOT + pBase;
#pragma unroll
                    for (int nt = 0; nt < 4; nt++) {
                        int p = warpN * 32 + nt * 8 + (lane & 3) * 2;
                        *(float2*)(rowp + p) =
                            make_float2(acc[mt][nt][h * 2], acc[mt][nt][h * 2 + 1]);
                    }
                }
            }
    } else if (writeMode == 1) {
#pragma unroll
        for (int mt = 0; mt < 4; mt++)
#pragma unroll
            for (int h = 0; h < 2; h++) {
                int o = oBase + warpM * 64 + mt * 16 + h * 8 + (lane >> 2);
                if (o < 3) {
                    float* rowp = out + ((size_t)bIdx * 3 + o) * NN + (pBase & (NN - 1));
#pragma unroll
                    for (int nt = 0; nt < 4; nt++) {
                        int p = warpN * 32 + nt * 8 + (lane & 3) * 2;
                        rowp[p]     = acc[mt][nt][h * 2];
                        rowp[p + 1] = acc[mt][nt][h * 2 + 1];
                    }
                }
            }
    }

    if (doStats) {
        float* red = (float*)dsm;
#pragma unroll
        for (int mt = 0; mt < 4; mt++)
#pragma unroll
            for (int h = 0; h < 2; h++) {
                float s = 0.f, q = 0.f, mx = -FLT_MAX;
#pragma unroll
                for (int nt = 0; nt < 4; nt++)
#pragma unroll
                    for (int e = 0; e < 2; e++) {
                        float v = acc[mt][nt][h * 2 + e];
                        s += v; q += v * v; mx = fmaxf(mx, v);
                    }
                s += __shfl_xor_sync(~0u, s, 1); s += __shfl_xor_sync(~0u, s, 2);
                q += __shfl_xor_sync(~0u, q, 1); q += __shfl_xor_sync(~0u, q, 2);
                mx = fmaxf(mx, __shfl_xor_sync(~0u, mx, 1));
                mx = fmaxf(mx, __shfl_xor_sync(~0u, mx, 2));
                if ((lane & 3) == 0) {
                    int row = warpM * 64 + mt * 16 + h * 8 + (lane >> 2);
                    red[warpN * M + row] = s;
                    red[NWN * M + warpN * M + row] = q;
                    if (doMax) red[2 * NWN * M + warpN * M + row] = mx;
                }
            }
        __syncthreads();
        if (tid < M) {
            float s = 0.f, q = 0.f, mx = -FLT_MAX;
#pragma unroll
            for (int wn = 0; wn < NWN; wn++) {
                s += red[wn * M + tid];
                q += red[NWN * M + wn * M + tid];
                if (doMax) mx = fmaxf(mx, red[2 * NWN * M + wn * M + tid]);
            }
            int o = oBase + tid;
            psum[(size_t)o * GXMAX + blockIdx.x] = s;
            pq[(size_t)o * GXMAX + blockIdx.x] = q;
            if (doMax) pmax[(size_t)o * GXMAX + blockIdx.x] = mx;
        }
    }
}

// ===================== BN finalize: warp per channel =====================
__global__ __launch_bounds__(256) void bn_fin(
    const float* __restrict__ ps, const float* __restrict__ pq,
    float* __restrict__ mean, float* __restrict__ rstd, int C, int gx)
{
    int w = threadIdx.x >> 5, lane = threadIdx.x & 31;
    int c = blockIdx.x * 8 + w;
    if (c >= C) return;
    float s = 0.f, q = 0.f;
    for (int j = lane; j < gx; j += 32) {
        s += ps[(size_t)c * GXMAX + j];
        q += pq[(size_t)c * GXMAX + j];
    }
#pragma unroll
    for (int o = 16; o; o >>= 1) {
        s += __shfl_xor_sync(~0u, s, o);
        q += __shfl_xor_sync(~0u, q, o);
    }
    if (lane == 0) {
        float m = s * (1.0f / BN_TOT);
        mean[c] = m;
        rstd[c] = rsqrtf(q * (1.0f / BN_TOT) - m * m + 1e-5f);
    }
}

// ============ gf (max over 8 tiles + BN) + bias6 fold, batch-blocked ========
__global__ __launch_bounds__(256) void gfbias6(
    const float* __restrict__ pm, const float* __restrict__ mean,
    const float* __restrict__ rstd, const float* __restrict__ W6,
    float* __restrict__ bias6)
{
    extern __shared__ float feat[];   // 4 * 4096 floats
    const int by = blockIdx.y;        // 8 groups of 4 batches
#pragma unroll
    for (int bb = 0; bb < 4; bb++) {
        int b = by * 4 + bb;
        for (int c = threadIdx.x; c < 1024; c += 256) {
            float mx = -FLT_MAX;
#pragma unroll
            for (int j = 0; j < 8; j++)
                mx = fmaxf(mx, pm[(size_t)c * GXMAX + b * 8 + j]);
            float g = (mx - mean[c]) * rstd[c];
            float t = tanhf(g);
            float q1 = 2.0f * t;
            float q2 = 3.75f * t * t - 0.75f;
            float q3 = 1.8666666666666667f * t * q2 - 0.8f * q1;
            feat[bb * 4096 + c * 4 + 0] = 1.0f;
            feat[bb * 4096 + c * 4 + 1] = q1;
            feat[bb * 4096 + c * 4 + 2] = q2;
            feat[bb * 4096 + c * 4 + 3] = q3;
        }
    }
    __syncthreads();
    const int o = blockIdx.x * 256 + threadIdx.x;
    float acc[4] = {0.f, 0.f, 0.f, 0.f};
    for (int c = 0; c < 1024; c++) {
        float4 w = *(const float4*)(W6 + ((size_t)(64 + c) * 512 + o) * 4);
#pragma unroll
        for (int bb = 0; bb < 4; bb++) {
            float4 f = *(const float4*)&feat[bb * 4096 + c * 4];
            acc[bb] += f.x * w.x + f.y * w.y + f.z * w.z + f.w * w.w;
        }
    }
#pragma unroll
    for (int bb = 0; bb < 4; bb++)
        bias6[(by * 4 + bb) * 512 + o] = acc[bb];
}

// ===================== host =====================
static const LayerP h_L[10] = {
    {  2,   64,   64,  128,       0},
    { 64,   64,  256,  128,    8192},
    { 64,   64,  256,  128,   40960},
    { 64,  128,  256,  128,   73728},
    {128, 1024,  512, 1024,  106496},
    { 64,  512,  256,  512,  630784},
    {512,  256, 2048,  256,  761856},
    {256,  128, 1024,  128, 1286144},
    {128,  128,  512,  128, 1417216},
    {128,    3,  512,  128, 1482752},
};

static constexpr int SMEM_TILE = 196608;

extern "C" void kernel_launch(void* const* d_in, const int* in_sizes, int n_in,
                              void* d_out, int out_size)
{
    (void)in_sizes; (void)n_in; (void)out_size;
    const float* x = (const float*)d_in[0];
    WPtrs wp;
    for (int i = 0; i < 10; i++) wp.p[i] = (const float*)d_in[1 + i];

    float* buf = nullptr;
    cudaGetSymbolAddress((void**)&buf, g_buf);
    __nv_bfloat16* whi = nullptr;
    __nv_bfloat16* wlo = nullptr;
    cudaGetSymbolAddress((void**)&whi, g_whi);
    cudaGetSymbolAddress((void**)&wlo, g_wlo);

    float* h1 = buf + OFF_H1;
    float* h2 = buf + OFF_H2;
    float* h3 = buf + OFF_H3;
    float* h4 = buf + OFF_H4;
    float* h6 = buf + OFF_H6;
    float* h7 = buf + OFF_H7;
    float* h8 = buf + OFF_H8;
    float* h9 = buf + OFF_H9;
    float* meanB = buf + OFF_MEAN;
    float* rstdB = buf + OFF_RSTD;
    float* bias6 = buf + OFF_B6;
    float* ps    = buf + OFF_PS;
    float* pqb   = buf + OFF_PQ;
    float* pm    = buf + OFF_PM;

    cudaFuncSetAttribute(kan_mma<4, 4, 128>,
                         cudaFuncAttributeMaxDynamicSharedMemorySize, SMEM_TILE);
    cudaFuncSetAttribute(kan_mma<2, 8, 256>,
                         cudaFuncAttributeMaxDynamicSharedMemorySize, SMEM_TILE);
    cudaFuncSetAttribute(gfbias6,
                         cudaFuncAttributeMaxDynamicSharedMemorySize, 65536);

    {
        dim3 g(2048, 10);
        wcvt_all<<<g, 256>>>(wp, whi, wlo);
    }

    auto M = [&](int s) { return meanB + s * 1024; };
    auto R = [&](int s) { return rstdB + s * 1024; };

    auto gbig = [&](int l, const float* Hin, const float* mn, const float* rs,
                    const float* bias, float* Hout, int wm, int st, int mx) {
        dim3 grid(BN_TOT / 128, h_L[l].rows / 256, 1);
        kan_mma<4, 4, 128><<<grid, 512, SMEM_TILE>>>(Hin, mn, rs,
            whi + h_L[l].woff, wlo + h_L[l].woff, bias, Hout, ps, pqb, pm,
            h_L[l].cin, h_L[l].cout, h_L[l].kp, h_L[l].kp / 64, wm, st, mx, 0);
    };
    auto gsm = [&](int l, const float* Hin, const float* mn, const float* rs,
                   const float* bias, float* Hout, int wm, int st, int mx, int ib) {
        dim3 grid(BN_TOT / 256, h_L[l].rows / 128, 1);
        kan_mma<2, 8, 256><<<grid, 512, SMEM_TILE>>>(Hin, mn, rs,
            whi + h_L[l].woff, wlo + h_L[l].woff, bias, Hout, ps, pqb, pm,
            h_L[l].cin, h_L[l].cout, h_L[l].kp, h_L[l].kp / 64, wm, st, mx, ib);
    };
    auto fin = [&](int slot, int C, int gx) {
        bn_fin<<<(C + 7) / 8, 256>>>(ps, pqb, M(slot), R(slot), C, gx);
    };

    gsm(0, x, nullptr, nullptr, nullptr, h1, 0, 1, 0, 1);   fin(0, 64, 128);
    gsm(1, h1, M(0), R(0), nullptr, h2, 0, 1, 0, 0);        fin(1, 64, 128);
    gsm(2, h2, M(1), R(1), nullptr, h3, 0, 1, 0, 0);        fin(2, 64, 128);
    gsm(3, h3, M(2), R(2), nullptr, h4, 0, 1, 0, 0);        fin(3, 128, 128);
    gbig(4, h4, M(3), R(3), nullptr, nullptr, 2, 1, 1);     fin(4, 1024, 256);

    {
        dim3 g(2, 8);
        gfbias6<<<g, 256, 65536>>>(pm, M(4), R(4), wp.p[5], bias6);
    }

    gbig(5, h2, M(1), R(1), bias6, h6, 0, 1, 0);            fin(5, 512, 256);
    gbig(6, h6, M(5), R(5), nullptr, h7, 0, 1, 0);          fin(6, 256, 256);
    gsm(7, h7, M(6), R(6), nullptr, h8, 0, 1, 0, 0);        fin(7, 128, 128);
    gsm(8, h8, M(7), R(7), nullptr, h9, 0, 1, 0, 0);        fin(8, 128, 128);
    gsm(9, h9, M(8), R(8), nullptr, (float*)d_out, 1, 0, 0, 0);
}

// round 10
// speedup vs baseline: 1.4572x; 1.0460x over previous
#include <cuda_runtime.h>
#include <cuda_bf16.h>
#include <math.h>
#include <float.h>
#include <stdint.h>

#define BB 32
#define NN 1024
#define BN_TOT 32768
#define GXMAX 256

#define SWZ128(o) ((o) ^ (((o) >> 3) & 0x70))

__device__ __forceinline__ uint32_t smem_u32(const void* p) {
    uint32_t a;
    asm("{ .reg .u64 t; cvta.to.shared.u64 t, %1; cvt.u32.u64 %0, t; }"
        : "=r"(a) : "l"(p));
    return a;
}
__device__ __forceinline__ uint32_t pack_bf2(float lo, float hi) {
    uint32_t r;
    asm("cvt.rn.bf16x2.f32 %0, %1, %2;" : "=r"(r) : "f"(hi), "f"(lo));
    return r;
}
// fast tanh: t = 1 - 2/(2^(2*log2e*v) + 1)
__device__ __forceinline__ float tanh_fast(float v) {
    float e;
    asm("ex2.approx.f32 %0, %1;" : "=f"(e) : "f"(v * 2.8853900817779268f));
    float r;
    asm("rcp.approx.f32 %0, %1;" : "=f"(r) : "f"(e + 1.0f));
    return fmaf(-2.0f, r, 1.0f);
}
__device__ __forceinline__ void ldm_x4(uint32_t* r, uint32_t addr) {
    asm volatile("ldmatrix.sync.aligned.m8n8.x4.shared.b16 {%0,%1,%2,%3}, [%4];"
                 : "=r"(r[0]), "=r"(r[1]), "=r"(r[2]), "=r"(r[3]) : "r"(addr));
}
__device__ __forceinline__ void mma16816(float* d, const uint32_t* a, const uint32_t* b) {
    asm volatile(
        "mma.sync.aligned.m16n8k16.row.col.f32.bf16.bf16.f32 "
        "{%0,%1,%2,%3}, {%4,%5,%6,%7}, {%8,%9}, {%0,%1,%2,%3};"
        : "+f"(d[0]), "+f"(d[1]), "+f"(d[2]), "+f"(d[3])
        : "r"(a[0]), "r"(a[1]), "r"(a[2]), "r"(a[3]), "r"(b[0]), "r"(b[1]));
}
__device__ __forceinline__ void cp16(uint32_t dst, const void* src) {
    asm volatile("cp.async.cg.shared.global [%0], [%1], 16;" :: "r"(dst), "l"(src));
}
__device__ __forceinline__ void cp_commit() {
    asm volatile("cp.async.commit_group;" ::: "memory");
}
__device__ __forceinline__ void cp_wait0() {
    asm volatile("cp.async.wait_group 0;" ::: "memory");
}

// ===================== scratch =====================
static constexpr size_t CH = (size_t)BN_TOT;
static constexpr size_t OFF_H1 = 0;
static constexpr size_t OFF_H2 = OFF_H1 + 64 * CH;
static constexpr size_t OFF_H3 = OFF_H2 + 64 * CH;
static constexpr size_t OFF_H4 = OFF_H3 + 64 * CH;
static constexpr size_t OFF_H6 = OFF_H4 + 128 * CH;
static constexpr size_t OFF_H7 = OFF_H6 + 512 * CH;
static constexpr size_t OFF_H8 = OFF_H7 + 256 * CH;
static constexpr size_t OFF_H9 = OFF_H8 + 128 * CH;
static constexpr size_t OFF_MEAN = OFF_H9 + 128 * CH;
static constexpr size_t OFF_RSTD = OFF_MEAN + 10 * 1024;
static constexpr size_t OFF_B6   = OFF_RSTD + 10 * 1024;
static constexpr size_t OFF_PS   = OFF_B6 + (size_t)BB * 512;
static constexpr size_t OFF_PQ   = OFF_PS + 1024 * (size_t)GXMAX;
static constexpr size_t OFF_PM   = OFF_PQ + 1024 * (size_t)GXMAX;
static constexpr size_t TOTAL_F  = OFF_PM + 1024 * (size_t)GXMAX;

__device__ float g_buf[TOTAL_F];

static constexpr size_t WTOT = 1548288;
__device__ __nv_bfloat16 g_whi[WTOT];
__device__ __nv_bfloat16 g_wlo[WTOT];

// ===================== layer table =====================
struct LayerP { int cin, cout, kp, rows; unsigned woff; };
__constant__ LayerP c_L[10] = {
    {  2,   64,   64,  128,       0},
    { 64,   64,  256,  128,    8192},
    { 64,   64,  256,  128,   40960},
    { 64,  128,  256,  128,   73728},
    {128, 1024,  512, 1024,  106496},
    { 64,  512,  256,  512,  630784},
    {512,  256, 2048,  256,  761856},
    {256,  128, 1024,  128, 1286144},
    {128,  128,  512,  128, 1417216},
    {128,    3,  512,  128, 1482752},
};
struct WPtrs { const float* p[10]; };

// ===================== weight convert (all layers, one launch) ==============
__global__ __launch_bounds__(256) void wcvt_all(
    WPtrs wp, __nv_bfloat16* __restrict__ hi, __nv_bfloat16* __restrict__ lo)
{
    const LayerP L = c_L[blockIdx.y];
    int idx = blockIdx.x * 256 + threadIdx.x;
    if (idx >= L.rows * L.kp) return;
    int r = idx / L.kp, k = idx - r * L.kp;
    int i = k >> 2, d = k & 3;
    float w = 0.0f;
    if (r < L.cout && i < L.cin)
        w = wp.p[blockIdx.y][((size_t)i * L.cout + r) * 4 + d];
    __nv_bfloat16 h = __float2bfloat16(w);
    hi[L.woff + idx] = h;
    lo[L.woff + idx] = __float2bfloat16(w - __bfloat162float(h));
}

// ===================== fused featurize + split-bf16 HMMA GEMM ==============
// 512 threads = 16 warps (4x4), warp tile 32x32. CTA tile 128 outs x 128 pts.
// Single-buffered smem 64KB -> 2 CTAs/SM (forced by launch_bounds).
static constexpr int S_WH = 0;
static constexpr int S_WL = 16384;
static constexpr int S_FH = 32768;
static constexpr int S_FL = 49152;
static constexpr int S_TOT = 65536;

__global__ __launch_bounds__(512, 2) void kan_mma(
    const float* __restrict__ Hin, const float* __restrict__ mean,
    const float* __restrict__ rstd,
    const __nv_bfloat16* __restrict__ Whi, const __nv_bfloat16* __restrict__ Wlo,
    const float* __restrict__ bias, float* __restrict__ out,
    float* __restrict__ psum, float* __restrict__ pq, float* __restrict__ pmax,
    int Cin, int Cout, int Kp, int nChunks,
    int writeMode /*0 normal,1 final,2 none*/, int doStats, int doMax,
    int inBatched)
{
    extern __shared__ __align__(1024) char dsm[];
    const uint32_t sb = smem_u32(dsm);
    const int tid = threadIdx.x;
    const int wid = tid >> 5;
    const int lane = tid & 31;
    const int warpM = wid >> 2;     // 0..3 : 32 out rows each
    const int warpN = wid & 3;      // 0..3 : 32 points each
    const int pBase = blockIdx.x * 128;
    const int oBase = blockIdx.y * 128;
    const int bIdx = pBase >> 10;
    const bool hasBN = (mean != nullptr);

    float acc[2][4][4];
#pragma unroll
    for (int mt = 0; mt < 2; mt++)
#pragma unroll
        for (int nt = 0; nt < 4; nt++)
#pragma unroll
            for (int e = 0; e < 4; e++) acc[mt][nt][e] = 0.0f;

    const int icl = tid >> 5;       // producer channel (0..15)
    const int pl  = tid & 31;       // producer point sub-index
    // hoisted feature store addresses (swizzle XOR constant across j)
    const uint32_t aF0 = sb + SWZ128(pl * 128 + icl * 8);

    auto stageW = [&](int kc) {
#pragma unroll
        for (int l = 0; l < 2; l++) {
            int idx = tid + l * 512;
            int row = idx >> 3, c16 = idx & 7;
            size_t g = (size_t)(oBase + row) * Kp + (size_t)kc * 64 + c16 * 8;
            uint32_t off = SWZ128(row * 128 + c16 * 16);
            cp16(sb + S_WH + off, Whi + g);
            cp16(sb + S_WL + off, Wlo + g);
        }
        cp_commit();
    };
    auto featStore = [&](int kc) {
        const int ch = kc * 16 + icl;
        const bool valid = ch < Cin;
        float nm = 0.f, rs = 0.f;
        if (hasBN) { if (valid) { rs = rstd[ch]; nm = -mean[ch] * rs; } }
        else if (valid) rs = 1.f;
        const float* hrow;
        if (inBatched)
            hrow = Hin + ((size_t)bIdx * Cin + (valid ? ch : 0)) * NN + (pBase & (NN - 1));
        else
            hrow = Hin + (size_t)(valid ? ch : 0) * BN_TOT + pBase;
#pragma unroll
        for (int j = 0; j < 4; j++) {
            float xv = valid ? hrow[pl + 32 * j] : 0.0f;
            float v = fmaf(xv, rs, nm);           // invalid -> 0
            float t = tanh_fast(v);
            float q1 = t + t;
            float q2 = fmaf(3.75f * t, t, -0.75f);
            float q3 = t * fmaf(1.8666666666666667f, q2, -1.6f);
            uint32_t u1 = __float_as_uint(q1) & 0xFFFF0000u;
            uint32_t u2 = __float_as_uint(q2) & 0xFFFF0000u;
            uint32_t u3 = __float_as_uint(q3) & 0xFFFF0000u;
            float l1 = q1 - __uint_as_float(u1);
            float l2 = q2 - __uint_as_float(u2);
            float l3 = q3 - __uint_as_float(u3);
            uint32_t w01 = __byte_perm(u1, 0x3F800000u, 0x3276);
            uint32_t w23 = __byte_perm(u2, u3, 0x7632);
            uint32_t l01 = pack_bf2(0.0f, l1);
            uint32_t l23 = pack_bf2(l2, l3);
            *(uint2*)(dsm + (aF0 - sb) + S_FH + j * 4096) = make_uint2(w01, w23);
            *(uint2*)(dsm + (aF0 - sb) + S_FL + j * 4096) = make_uint2(l01, l23);
        }
    };
    auto doMMA = [&]() {
#pragma unroll
        for (int ks = 0; ks < 4; ks++) {
            uint32_t ah[2][4], al[2][4];
#pragma unroll
            for (int mt = 0; mt < 2; mt++) {
                int r = warpM * 32 + mt * 16 + (lane & 15);
                int cB = ks * 32 + (lane >> 4) * 16;
                uint32_t a = sb + SWZ128(r * 128 + cB);
                ldm_x4(ah[mt], a + S_WH);
                ldm_x4(al[mt], a + S_WL);
            }
#pragma unroll
            for (int ntp = 0; ntp < 2; ntp++) {
                uint32_t fh[4], fl[4];
                int rN = warpN * 32 + ntp * 16 + ((lane >> 4) << 3) + (lane & 7);
                int cB = ks * 32 + ((lane >> 3) & 1) * 16;
                uint32_t a = sb + SWZ128(rN * 128 + cB);
                ldm_x4(fh, a + S_FH);
                ldm_x4(fl, a + S_FL);
#pragma unroll
                for (int mt = 0; mt < 2; mt++)
#pragma unroll
                    for (int s = 0; s < 2; s++) {
                        int nt = 2 * ntp + s;
                        mma16816(acc[mt][nt], ah[mt], &fh[2 * s]);
                        mma16816(acc[mt][nt], al[mt], &fh[2 * s]);
                        mma16816(acc[mt][nt], ah[mt], &fl[2 * s]);
                    }
            }
        }
    };

    // ---- serial chunk loop, cross-CTA overlap hides latency ----
    stageW(0);
    for (int kc = 0; kc < nChunks; kc++) {
        featStore(kc);          // overlaps in-flight weight cp.async
        cp_wait0();
        __syncthreads();
        doMMA();
        __syncthreads();
        if (kc + 1 < nChunks) stageW(kc + 1);
    }

    // ---- epilogue ----
#pragma unroll
    for (int mt = 0; mt < 2; mt++)
#pragma unroll
        for (int h = 0; h < 2; h++) {
            int o = oBase + warpM * 32 + mt * 16 + h * 8 + (lane >> 2);
            float bv = 0.f;
            if (bias && o < Cout) bv = bias[bIdx * Cout + o];
            if (bv != 0.f)
#pragma unroll
                for (int nt = 0; nt < 4; nt++) {
                    acc[mt][nt][h * 2 + 0] += bv;
                    acc[mt][nt][h * 2 + 1] += bv;
                }
        }

    if (writeMode == 0) {
#pragma unroll
        for (int mt = 0; mt < 2; mt++)
#pragma unroll
            for (int h = 0; h < 2; h++) {
                int o = oBase + warpM * 32 + mt * 16 + h * 8 + (lane >> 2);
                if (o < Cout) {
                    float* rowp = out + (size_t)o * BN_TOT + pBase;
#pragma unroll
                    for (int nt = 0; nt < 4; nt++) {
                        int p = warpN * 32 + nt * 8 + (lane & 3) * 2;
                        *(float2*)(rowp + p) =
                            make_float2(acc[mt][nt][h * 2], acc[mt][nt][h * 2 + 1]);
                    }
                }
            }
    } else if (writeMode == 1) {
#pragma unroll
        for (int mt = 0; mt < 2; mt++)
#pragma unroll
            for (int h = 0; h < 2; h++) {
                int o = oBase + warpM * 32 + mt * 16 + h * 8 + (lane >> 2);
                if (o < 3) {
                    float* rowp = out + ((size_t)bIdx * 3 + o) * NN + (pBase & (NN - 1));
#pragma unroll
                    for (int nt = 0; nt < 4; nt++) {
                        int p = warpN * 32 + nt * 8 + (lane & 3) * 2;
                        rowp[p]     = acc[mt][nt][h * 2];
                        rowp[p + 1] = acc[mt][nt][h * 2 + 1];
                    }
                }
            }
    }

    if (doStats) {
        float* red = (float*)dsm;
#pragma unroll
        for (int mt = 0; mt < 2; mt++)
#pragma unroll
            for (int h = 0; h < 2; h++) {
                float s = 0.f, q = 0.f, mx = -FLT_MAX;
#pragma unroll
                for (int nt = 0; nt < 4; nt++)
#pragma unroll
                    for (int e = 0; e < 2; e++) {
                        float v = acc[mt][nt][h * 2 + e];
                        s += v; q += v * v; mx = fmaxf(mx, v);
                    }
                s += __shfl_xor_sync(~0u, s, 1); s += __shfl_xor_sync(~0u, s, 2);
                q += __shfl_xor_sync(~0u, q, 1); q += __shfl_xor_sync(~0u, q, 2);
                mx = fmaxf(mx, __shfl_xor_sync(~0u, mx, 1));
                mx = fmaxf(mx, __shfl_xor_sync(~0u, mx, 2));
                if ((lane & 3) == 0) {
                    int row = warpM * 32 + mt * 16 + h * 8 + (lane >> 2);
                    red[warpN * 128 + row] = s;
                    red[512 + warpN * 128 + row] = q;
                    if (doMax) red[1024 + warpN * 128 + row] = mx;
                }
            }
        __syncthreads();
        if (tid < 128) {
            float s = 0.f, q = 0.f, mx = -FLT_MAX;
#pragma unroll
            for (int wn = 0; wn < 4; wn++) {
                s += red[wn * 128 + tid];
                q += red[512 + wn * 128 + tid];
                if (doMax) mx = fmaxf(mx, red[1024 + wn * 128 + tid]);
            }
            int o = oBase + tid;
            psum[(size_t)o * GXMAX + blockIdx.x] = s;
            pq[(size_t)o * GXMAX + blockIdx.x] = q;
            if (doMax) pmax[(size_t)o * GXMAX + blockIdx.x] = mx;
        }
    }
}

// ===================== BN finalize: warp per channel =====================
__global__ __launch_bounds__(256) void bn_fin(
    const float* __restrict__ ps, const float* __restrict__ pq,
    float* __restrict__ mean, float* __restrict__ rstd, int C)
{
    int w = threadIdx.x >> 5, lane = threadIdx.x & 31;
    int c = blockIdx.x * 8 + w;
    if (c >= C) return;
    float s = 0.f, q = 0.f;
    for (int j = lane; j < 256; j += 32) {
        s += ps[(size_t)c * GXMAX + j];
        q += pq[(size_t)c * GXMAX + j];
    }
#pragma unroll
    for (int o = 16; o; o >>= 1) {
        s += __shfl_xor_sync(~0u, s, o);
        q += __shfl_xor_sync(~0u, q, o);
    }
    if (lane == 0) {
        float m = s * (1.0f / BN_TOT);
        mean[c] = m;
        rstd[c] = rsqrtf(q * (1.0f / BN_TOT) - m * m + 1e-5f);
    }
}

// ============ gf (max over 8 tiles + BN) + bias6 fold (R7 form) ============
__global__ __launch_bounds__(256) void gfbias6(
    const float* __restrict__ pm, const float* __restrict__ mean,
    const float* __restrict__ rstd, const float* __restrict__ W6,
    float* __restrict__ bias6)
{
    const int b = blockIdx.y;
    __shared__ float feat[4096];
    for (int c = threadIdx.x; c < 1024; c += 256) {
        float mx = -FLT_MAX;
#pragma unroll
        for (int j = 0; j < 8; j++)
            mx = fmaxf(mx, pm[(size_t)c * GXMAX + b * 8 + j]);
        float g = (mx - mean[c]) * rstd[c];
        float t = tanhf(g);
        float q1 = 2.0f * t;
        float q2 = 3.75f * t * t - 0.75f;
        float q3 = 1.8666666666666667f * t * q2 - 0.8f * q1;
        feat[c * 4 + 0] = 1.0f;
        feat[c * 4 + 1] = q1;
        feat[c * 4 + 2] = q2;
        feat[c * 4 + 3] = q3;
    }
    __syncthreads();
    const int o = blockIdx.x * 256 + threadIdx.x;
    float s = 0.f;
    for (int c = 0; c < 1024; c++) {
        float4 w4 = *(const float4*)(W6 + ((size_t)(64 + c) * 512 + o) * 4);
        s += feat[c * 4 + 0] * w4.x + feat[c * 4 + 1] * w4.y +
             feat[c * 4 + 2] * w4.z + feat[c * 4 + 3] * w4.w;
    }
    bias6[b * 512 + o] = s;
}

// ===================== host =====================
static const LayerP h_L[10] = {
    {  2,   64,   64,  128,       0},
    { 64,   64,  256,  128,    8192},
    { 64,   64,  256,  128,   40960},
    { 64,  128,  256,  128,   73728},
    {128, 1024,  512, 1024,  106496},
    { 64,  512,  256,  512,  630784},
    {512,  256, 2048,  256,  761856},
    {256,  128, 1024,  128, 1286144},
    {128,  128,  512,  128, 1417216},
    {128,    3,  512,  128, 1482752},
};

extern "C" void kernel_launch(void* const* d_in, const int* in_sizes, int n_in,
                              void* d_out, int out_size)
{
    (void)in_sizes; (void)n_in; (void)out_size;
    const float* x = (const float*)d_in[0];
    WPtrs wp;
    for (int i = 0; i < 10; i++) wp.p[i] = (const float*)d_in[1 + i];

    float* buf = nullptr;
    cudaGetSymbolAddress((void**)&buf, g_buf);
    __nv_bfloat16* whi = nullptr;
    __nv_bfloat16* wlo = nullptr;
    cudaGetSymbolAddress((void**)&whi, g_whi);
    cudaGetSymbolAddress((void**)&wlo, g_wlo);

    float* h1 = buf + OFF_H1;
    float* h2 = buf + OFF_H2;
    float* h3 = buf + OFF_H3;
    float* h4 = buf + OFF_H4;
    float* h6 = buf + OFF_H6;
    float* h7 = buf + OFF_H7;
    float* h8 = buf + OFF_H8;
    float* h9 = buf + OFF_H9;
    float* meanB = buf + OFF_MEAN;
    float* rstdB = buf + OFF_RSTD;
    float* bias6 = buf + OFF_B6;
    float* ps    = buf + OFF_PS;
    float* pqb   = buf + OFF_PQ;
    float* pm    = buf + OFF_PM;

    cudaFuncSetAttribute(kan_mma, cudaFuncAttributeMaxDynamicSharedMemorySize, S_TOT);

    {
        dim3 g(2048, 10);
        wcvt_all<<<g, 256>>>(wp, whi, wlo);
    }

    auto M = [&](int s) { return meanB + s * 1024; };
    auto R = [&](int s) { return rstdB + s * 1024; };

    auto gemm = [&](int l, const float* Hin, const float* mn, const float* rs,
                    const float* bias, float* Hout, int wm, int st, int mx, int ib) {
        dim3 grid(BN_TOT / 128, h_L[l].rows / 128, 1);
        kan_mma<<<grid, 512, S_TOT>>>(Hin, mn, rs, whi + h_L[l].woff,
            wlo + h_L[l].woff, bias, Hout, ps, pqb, pm,
            h_L[l].cin, h_L[l].cout, h_L[l].kp, h_L[l].kp / 64, wm, st, mx, ib);
    };
    auto fin = [&](int slot, int C) {
        bn_fin<<<(C + 7) / 8, 256>>>(ps, pqb, M(slot), R(slot), C);
    };

    gemm(0, x, nullptr, nullptr, nullptr, h1, 0, 1, 0, 1);  fin(0, 64);
    gemm(1, h1, M(0), R(0), nullptr, h2, 0, 1, 0, 0);       fin(1, 64);
    gemm(2, h2, M(1), R(1), nullptr, h3, 0, 1, 0, 0);       fin(2, 64);
    gemm(3, h3, M(2), R(2), nullptr, h4, 0, 1, 0, 0);       fin(3, 128);
    gemm(4, h4, M(3), R(3), nullptr, nullptr, 2, 1, 1, 0);  fin(4, 1024);

    {
        dim3 g(2, BB);
        gfbias6<<<g, 256>>>(pm, M(4), R(4), wp.p[5], bias6);
    }

    gemm(5, h2, M(1), R(1), bias6, h6, 0, 1, 0, 0);         fin(5, 512);
    gemm(6, h6, M(5), R(5), nullptr, h7, 0, 1, 0, 0);       fin(6, 256);
    gemm(7, h7, M(6), R(6), nullptr, h8, 0, 1, 0, 0);       fin(7, 128);
    gemm(8, h8, M(7), R(7), nullptr, h9, 0, 1, 0, 0);       fin(8, 128);
    gemm(9, h9, M(8), R(8), nullptr, (float*)d_out, 1, 0, 0, 0);
}

// round 11
// speedup vs baseline: 1.5368x; 1.0546x over previous
#include <cuda_runtime.h>
#include <cuda_bf16.h>
#include <math.h>
#include <float.h>
#include <stdint.h>

#define BB 32
#define NN 1024
#define BN_TOT 32768
#define GXMAX 256

#define SWZ128(o) ((o) ^ (((o) >> 3) & 0x70))

__device__ __forceinline__ uint32_t smem_u32(const void* p) {
    uint32_t a;
    asm("{ .reg .u64 t; cvta.to.shared.u64 t, %1; cvt.u32.u64 %0, t; }"
        : "=r"(a) : "l"(p));
    return a;
}
__device__ __forceinline__ uint32_t pack_bf2(float lo, float hi) {
    uint32_t r;
    asm("cvt.rn.bf16x2.f32 %0, %1, %2;" : "=r"(r) : "f"(hi), "f"(lo));
    return r;
}
// fast tanh: t = 1 - 2/(2^(2*log2e*v) + 1); err ~1e-6
__device__ __forceinline__ float tanh_fast(float v) {
    float e;
    asm("ex2.approx.f32 %0, %1;" : "=f"(e) : "f"(v * 2.8853900817779268f));
    float r;
    asm("rcp.approx.f32 %0, %1;" : "=f"(r) : "f"(e + 1.0f));
    return fmaf(-2.0f, r, 1.0f);
}
__device__ __forceinline__ void ldm_x4(uint32_t* r, uint32_t addr) {
    asm volatile("ldmatrix.sync.aligned.m8n8.x4.shared.b16 {%0,%1,%2,%3}, [%4];"
                 : "=r"(r[0]), "=r"(r[1]), "=r"(r[2]), "=r"(r[3]) : "r"(addr));
}
__device__ __forceinline__ void mma16816(float* d, const uint32_t* a, const uint32_t* b) {
    asm volatile(
        "mma.sync.aligned.m16n8k16.row.col.f32.bf16.bf16.f32 "
        "{%0,%1,%2,%3}, {%4,%5,%6,%7}, {%8,%9}, {%0,%1,%2,%3};"
        : "+f"(d[0]), "+f"(d[1]), "+f"(d[2]), "+f"(d[3])
        : "r"(a[0]), "r"(a[1]), "r"(a[2]), "r"(a[3]), "r"(b[0]), "r"(b[1]));
}
__device__ __forceinline__ void cp16(uint32_t dst, const void* src) {
    asm volatile("cp.async.cg.shared.global [%0], [%1], 16;" :: "r"(dst), "l"(src));
}
__device__ __forceinline__ void cp_commit() {
    asm volatile("cp.async.commit_group;" ::: "memory");
}
__device__ __forceinline__ void cp_wait0() {
    asm volatile("cp.async.wait_group 0;" ::: "memory");
}

// ===================== scratch =====================
static constexpr size_t CH = (size_t)BN_TOT;
static constexpr size_t OFF_H1 = 0;
static constexpr size_t OFF_H2 = OFF_H1 + 64 * CH;
static constexpr size_t OFF_H3 = OFF_H2 + 64 * CH;
static constexpr size_t OFF_H4 = OFF_H3 + 64 * CH;
static constexpr size_t OFF_H6 = OFF_H4 + 128 * CH;
static constexpr size_t OFF_H7 = OFF_H6 + 512 * CH;
static constexpr size_t OFF_H8 = OFF_H7 + 256 * CH;
static constexpr size_t OFF_H9 = OFF_H8 + 128 * CH;
static constexpr size_t OFF_MEAN = OFF_H9 + 128 * CH;
static constexpr size_t OFF_RSTD = OFF_MEAN + 10 * 1024;
static constexpr size_t OFF_B6   = OFF_RSTD + 10 * 1024;
static constexpr size_t OFF_PS   = OFF_B6 + (size_t)BB * 512;
static constexpr size_t OFF_PQ   = OFF_PS + 1024 * (size_t)GXMAX;
static constexpr size_t OFF_PM   = OFF_PQ + 1024 * (size_t)GXMAX;
static constexpr size_t TOTAL_F  = OFF_PM + 1024 * (size_t)GXMAX;

__device__ float g_buf[TOTAL_F];

static constexpr size_t WTOT = 1548288;
__device__ __nv_bfloat16 g_whi[WTOT];
__device__ __nv_bfloat16 g_wlo[WTOT];

// ===================== layer table =====================
struct LayerP { int cin, cout, kp, rows; unsigned woff; };
__constant__ LayerP c_L[10] = {
    {  2,   64,   64,  128,       0},
    { 64,   64,  256,  128,    8192},
    { 64,   64,  256,  128,   40960},
    { 64,  128,  256,  128,   73728},
    {128, 1024,  512, 1024,  106496},
    { 64,  512,  256,  512,  630784},
    {512,  256, 2048,  256,  761856},
    {256,  128, 1024,  128, 1286144},
    {128,  128,  512,  128, 1417216},
    {128,    3,  512,  128, 1482752},
};
struct WPtrs { const float* p[10]; };

// ===================== weight convert (all layers, one launch) ==============
__global__ __launch_bounds__(256) void wcvt_all(
    WPtrs wp, __nv_bfloat16* __restrict__ hi, __nv_bfloat16* __restrict__ lo)
{
    const LayerP L = c_L[blockIdx.y];
    int idx = blockIdx.x * 256 + threadIdx.x;
    if (idx >= L.rows * L.kp) return;
    int r = idx / L.kp, k = idx - r * L.kp;
    int i = k >> 2, d = k & 3;
    float w = 0.0f;
    if (r < L.cout && i < L.cin)
        w = wp.p[blockIdx.y][((size_t)i * L.cout + r) * 4 + d];
    __nv_bfloat16 h = __float2bfloat16(w);
    hi[L.woff + idx] = h;
    lo[L.woff + idx] = __float2bfloat16(w - __bfloat162float(h));
}

// ===================== fused featurize + split-bf16 HMMA GEMM ==============
// 512 threads = 16 warps (NWM x NWN), warp tile 64x32.
// CTA tile: M = 64*NWM outs x NT points. 2 smem stages of (M+NT)*256 bytes.
template <int NWM, int NWN, int NT>
__global__ __launch_bounds__(512) void kan_mma(
    const float* __restrict__ Hin, const float* __restrict__ mean,
    const float* __restrict__ rstd,
    const __nv_bfloat16* __restrict__ Whi, const __nv_bfloat16* __restrict__ Wlo,
    const float* __restrict__ bias, float* __restrict__ out,
    float* __restrict__ psum, float* __restrict__ pq, float* __restrict__ pmax,
    int Cin, int Cout, int Kp, int nChunks,
    int writeMode /*0 normal,1 final,2 none*/, int doStats, int doMax,
    int inBatched)
{
    constexpr int M = 64 * NWM;
    constexpr int S_WH = 0;
    constexpr int S_WL = M * 128;
    constexpr int S_FH = 2 * M * 128;
    constexpr int S_FL = 2 * M * 128 + NT * 128;
    constexpr int S_STG = (M + NT) * 256;
    constexpr int NJ = NT / 32;

    extern __shared__ __align__(1024) char dsm[];
    const uint32_t sb = smem_u32(dsm);
    const int tid = threadIdx.x;
    const int wid = tid >> 5;
    const int lane = tid & 31;
    const int warpM = wid / NWN;    // 0..NWM-1 : 64 out rows each
    const int warpN = wid % NWN;    // 0..NWN-1 : 32 points each
    const int pBase = blockIdx.x * NT;
    const int oBase = blockIdx.y * M;
    const int bIdx = pBase >> 10;
    const bool hasBN = (mean != nullptr);

    float acc[4][4][4];
#pragma unroll
    for (int mt = 0; mt < 4; mt++)
#pragma unroll
        for (int nt = 0; nt < 4; nt++)
#pragma unroll
            for (int e = 0; e < 4; e++) acc[mt][nt][e] = 0.0f;

    const int icl = tid >> 5;       // producer channel (0..15)
    const int pl  = tid & 31;       // producer point sub-index

    auto stageW = [&](int kc, int sOff) {
#pragma unroll
        for (int l = 0; l < M / 64; l++) {
            int idx = tid + l * 512;
            int row = idx >> 3, c16 = idx & 7;
            size_t g = (size_t)(oBase + row) * Kp + (size_t)kc * 64 + c16 * 8;
            uint32_t off = SWZ128(row * 128 + c16 * 16);
            cp16(sb + sOff + S_WH + off, Whi + g);
            cp16(sb + sOff + S_WL + off, Wlo + g);
        }
    };
    auto featStore = [&](int kc, int sOff) {
        const int ch = kc * 16 + icl;
        const bool valid = ch < Cin;
        float mn = 0.f, rs = 1.f;
        if (hasBN && valid) { mn = mean[ch]; rs = rstd[ch]; }
        const float* hrow;
        if (inBatched)
            hrow = Hin + ((size_t)bIdx * Cin + (valid ? ch : 0)) * NN + (pBase & (NN - 1));
        else
            hrow = Hin + (size_t)(valid ? ch : 0) * BN_TOT + pBase;
        float av[NJ];
#pragma unroll
        for (int j = 0; j < NJ; j++)
            av[j] = valid ? hrow[pl + 32 * j] : 0.0f;
#pragma unroll
        for (int j = 0; j < NJ; j++) {
            const int p = pl + 32 * j;
            float v = hasBN ? (av[j] - mn) * rs : av[j];
            float t = tanh_fast(v);
            float q1 = 2.0f * t;
            float q2 = 3.75f * t * t - 0.75f;
            float q3 = 1.8666666666666667f * t * q2 - 0.8f * q1;
            uint32_t w01 = pack_bf2(1.0f, q1);
            uint32_t w23 = pack_bf2(q2, q3);
            float h1f = __uint_as_float(w01 & 0xFFFF0000u);
            float h2f = __uint_as_float(w23 << 16);
            float h3f = __uint_as_float(w23 & 0xFFFF0000u);
            uint32_t l01 = pack_bf2(0.0f, q1 - h1f);
            uint32_t l23 = pack_bf2(q2 - h2f, q3 - h3f);
            int o0 = SWZ128(p * 128 + icl * 8);
            *(uint2*)(dsm + sOff + S_FH + o0) = make_uint2(w01, w23);
            *(uint2*)(dsm + sOff + S_FL + o0) = make_uint2(l01, l23);
        }
    };
    auto doMMA = [&](int sOff) {
#pragma unroll
        for (int ks = 0; ks < 4; ks++) {
            uint32_t ah[4][4], al[4][4];
#pragma unroll
            for (int mt = 0; mt < 4; mt++) {
                int r = warpM * 64 + mt * 16 + (lane & 15);
                int cB = ks * 32 + (lane >> 4) * 16;
                uint32_t a = sb + sOff + SWZ128(r * 128 + cB);
                ldm_x4(ah[mt], a + S_WH);
                ldm_x4(al[mt], a + S_WL);
            }
#pragma unroll
            for (int ntp = 0; ntp < 2; ntp++) {
                uint32_t fh[4], fl[4];
                int rN = warpN * 32 + ntp * 16 + ((lane >> 4) << 3) + (lane & 7);
                int cB = ks * 32 + ((lane >> 3) & 1) * 16;
                uint32_t a = sb + sOff + SWZ128(rN * 128 + cB);
                ldm_x4(fh, a + S_FH);
                ldm_x4(fl, a + S_FL);
#pragma unroll
                for (int mt = 0; mt < 4; mt++)
#pragma unroll
                    for (int s = 0; s < 2; s++) {
                        int nt = 2 * ntp + s;
                        mma16816(acc[mt][nt], ah[mt], &fh[2 * s]);
                        mma16816(acc[mt][nt], al[mt], &fh[2 * s]);
                        mma16816(acc[mt][nt], ah[mt], &fl[2 * s]);
                    }
            }
        }
    };

    // ---- prologue ----
    stageW(0, 0); cp_commit();
    featStore(0, 0);
    cp_wait0();
    __syncthreads();

    // ---- pipelined main loop ----
    for (int kc = 0; kc < nChunks; kc++) {
        const int sOff = (kc & 1) ? S_STG : 0;
        const int nOff = (kc & 1) ? 0 : S_STG;
        const bool more = (kc + 1 < nChunks);
        if (more) {
            stageW(kc + 1, nOff); cp_commit();
        }
        doMMA(sOff);
        if (more) {
            featStore(kc + 1, nOff);
            cp_wait0();
        }
        __syncthreads();
    }

    // ---- epilogue ----
#pragma unroll
    for (int mt = 0; mt < 4; mt++)
#pragma unroll
        for (int h = 0; h < 2; h++) {
            int o = oBase + warpM * 64 + mt * 16 + h * 8 + (lane >> 2);
            float bv = 0.f;
            if (bias && o < Cout) bv = bias[bIdx * Cout + o];
            if (bv != 0.f)
#pragma unroll
                for (int nt = 0; nt < 4; nt++) {
                    acc[mt][nt][h * 2 + 0] += bv;
                    acc[mt][nt][h * 2 + 1] += bv;
                }
        }

    if (writeMode == 0) {
#pragma unroll
        for (int mt = 0; mt < 4; mt++)
#pragma unroll
            for (int h = 0; h < 2; h++) {
                int o = oBase + warpM * 64 + mt * 16 + h * 8 + (lane >> 2);
                if (o < Cout) {
                    float* rowp = out + (size_t)o * BN_TOT + pBase;
#pragma unroll
                    for (int nt = 0; nt < 4; nt++) {
                        int p = warpN * 32 + nt * 8 + (lane & 3) * 2;
                        *(float2*)(rowp + p) =
                            make_float2(acc[mt][nt][h * 2], acc[mt][nt][h * 2 + 1]);
                    }
                }
            }
    } else if (writeMode == 1) {
#pragma unroll
        for (int mt = 0; mt < 4; mt++)
#pragma unroll
            for (int h = 0; h < 2; h++) {
                int o = oBase + warpM * 64 + mt * 16 + h * 8 + (lane >> 2);
                if (o < 3) {
                    float* rowp = out + ((size_t)bIdx * 3 + o) * NN + (pBase & (NN - 1));
#pragma unroll
                    for (int nt = 0; nt < 4; nt++) {
                        int p = warpN * 32 + nt * 8 + (lane & 3) * 2;
                        rowp[p]     = acc[mt][nt][h * 2];
                        rowp[p + 1] = acc[mt][nt][h * 2 + 1];
                    }
                }
            }
    }

    if (doStats) {
        float* red = (float*)dsm;
#pragma unroll
        for (int mt = 0; mt < 4; mt++)
#pragma unroll
            for (int h = 0; h < 2; h++) {
                float s = 0.f, q = 0.f, mx = -FLT_MAX;
#pragma unroll
                for (int nt = 0; nt < 4; nt++)
#pragma unroll
                    for (int e = 0; e < 2; e++) {
                        float v = acc[mt][nt][h * 2 + e];
                        s += v; q += v * v; mx = fmaxf(mx, v);
                    }
                s += __shfl_xor_sync(~0u, s, 1); s += __shfl_xor_sync(~0u, s, 2);
                q += __shfl_xor_sync(~0u, q, 1); q += __shfl_xor_sync(~0u, q, 2);
                mx = fmaxf(mx, __shfl_xor_sync(~0u, mx, 1));
                mx = fmaxf(mx, __shfl_xor_sync(~0u, mx, 2));
                if ((lane & 3) == 0) {
                    int row = warpM * 64 + mt * 16 + h * 8 + (lane >> 2);
                    red[warpN * M + row] = s;
                    red[NWN * M + warpN * M + row] = q;
                    if (doMax) red[2 * NWN * M + warpN * M + row] = mx;
                }
            }
        __syncthreads();
        if (tid < M) {
            float s = 0.f, q = 0.f, mx = -FLT_MAX;
#pragma unroll
            for (int wn = 0; wn < NWN; wn++) {
                s += red[wn * M + tid];
                q += red[NWN * M + wn * M + tid];
                if (doMax) mx = fmaxf(mx, red[2 * NWN * M + wn * M + tid]);
            }
            int o = oBase + tid;
            psum[(size_t)o * GXMAX + blockIdx.x] = s;
            pq[(size_t)o * GXMAX + blockIdx.x] = q;
            if (doMax) pmax[(size_t)o * GXMAX + blockIdx.x] = mx;
        }
    }
}

// ===================== BN finalize: warp per channel =====================
__global__ __launch_bounds__(256) void bn_fin(
    const float* __restrict__ ps, const float* __restrict__ pq,
    float* __restrict__ mean, float* __restrict__ rstd, int C, int gx)
{
    int w = threadIdx.x >> 5, lane = threadIdx.x & 31;
    int c = blockIdx.x * 8 + w;
    if (c >= C) return;
    float s = 0.f, q = 0.f;
    for (int j = lane; j < gx; j += 32) {
        s += ps[(size_t)c * GXMAX + j];
        q += pq[(size_t)c * GXMAX + j];
    }
#pragma unroll
    for (int o = 16; o; o >>= 1) {
        s += __shfl_xor_sync(~0u, s, o);
        q += __shfl_xor_sync(~0u, q, o);
    }
    if (lane == 0) {
        float m = s * (1.0f / BN_TOT);
        mean[c] = m;
        rstd[c] = rsqrtf(q * (1.0f / BN_TOT) - m * m + 1e-5f);
    }
}

// ============ gf (max over 8 tiles + BN) + bias6 fold (R7 64-block form) ====
__global__ __launch_bounds__(256) void gfbias6(
    const float* __restrict__ pm, const float* __restrict__ mean,
    const float* __restrict__ rstd, const float* __restrict__ W6,
    float* __restrict__ bias6)
{
    const int b = blockIdx.y;
    __shared__ float feat[4096];
    for (int c = threadIdx.x; c < 1024; c += 256) {
        float mx = -FLT_MAX;
#pragma unroll
        for (int j = 0; j < 8; j++)   // L5 uses NT=128 -> 8 tiles per batch
            mx = fmaxf(mx, pm[(size_t)c * GXMAX + b * 8 + j]);
        float g = (mx - mean[c]) * rstd[c];
        float t = tanhf(g);
        float q1 = 2.0f * t;
        float q2 = 3.75f * t * t - 0.75f;
        float q3 = 1.8666666666666667f * t * q2 - 0.8f * q1;
        feat[c * 4 + 0] = 1.0f;
        feat[c * 4 + 1] = q1;
        feat[c * 4 + 2] = q2;
        feat[c * 4 + 3] = q3;
    }
    __syncthreads();
    const int o = blockIdx.x * 256 + threadIdx.x;
    float s = 0.f;
    for (int c = 0; c < 1024; c++) {
        float4 w4 = *(const float4*)(W6 + ((size_t)(64 + c) * 512 + o) * 4);
        s += feat[c * 4 + 0] * w4.x + feat[c * 4 + 1] * w4.y +
             feat[c * 4 + 2] * w4.z + feat[c * 4 + 3] * w4.w;
    }
    bias6[b * 512 + o] = s;
}

// ===================== host =====================
static const LayerP h_L[10] = {
    {  2,   64,   64,  128,       0},
    { 64,   64,  256,  128,    8192},
    { 64,   64,  256,  128,   40960},
    { 64,  128,  256,  128,   73728},
    {128, 1024,  512, 1024,  106496},
    { 64,  512,  256,  512,  630784},
    {512,  256, 2048,  256,  761856},
    {256,  128, 1024,  128, 1286144},
    {128,  128,  512,  128, 1417216},
    {128,    3,  512,  128, 1482752},
};

static constexpr int SMEM_TILE = 196608;

extern "C" void kernel_launch(void* const* d_in, const int* in_sizes, int n_in,
                              void* d_out, int out_size)
{
    (void)in_sizes; (void)n_in; (void)out_size;
    const float* x = (const float*)d_in[0];
    WPtrs wp;
    for (int i = 0; i < 10; i++) wp.p[i] = (const float*)d_in[1 + i];

    float* buf = nullptr;
    cudaGetSymbolAddress((void**)&buf, g_buf);
    __nv_bfloat16* whi = nullptr;
    __nv_bfloat16* wlo = nullptr;
    cudaGetSymbolAddress((void**)&whi, g_whi);
    cudaGetSymbolAddress((void**)&wlo, g_wlo);

    float* h1 = buf + OFF_H1;
    float* h2 = buf + OFF_H2;
    float* h3 = buf + OFF_H3;
    float* h4 = buf + OFF_H4;
    float* h6 = buf + OFF_H6;
    float* h7 = buf + OFF_H7;
    float* h8 = buf + OFF_H8;
    float* h9 = buf + OFF_H9;
    float* meanB = buf + OFF_MEAN;
    float* rstdB = buf + OFF_RSTD;
    float* bias6 = buf + OFF_B6;
    float* ps    = buf + OFF_PS;
    float* pqb   = buf + OFF_PQ;
    float* pm    = buf + OFF_PM;

    cudaFuncSetAttribute(kan_mma<4, 4, 128>,
                         cudaFuncAttributeMaxDynamicSharedMemorySize, SMEM_TILE);
    cudaFuncSetAttribute(kan_mma<2, 8, 256>,
                         cudaFuncAttributeMaxDynamicSharedMemorySize, SMEM_TILE);

    {
        dim3 g(2048, 10);
        wcvt_all<<<g, 256>>>(wp, whi, wlo);
    }

    auto M = [&](int s) { return meanB + s * 1024; };
    auto R = [&](int s) { return rstdB + s * 1024; };

    auto gbig = [&](int l, const float* Hin, const float* mn, const float* rs,
                    const float* bias, float* Hout, int wm, int st, int mx) {
        dim3 grid(BN_TOT / 128, h_L[l].rows / 256, 1);
        kan_mma<4, 4, 128><<<grid, 512, SMEM_TILE>>>(Hin, mn, rs,
            whi + h_L[l].woff, wlo + h_L[l].woff, bias, Hout, ps, pqb, pm,
            h_L[l].cin, h_L[l].cout, h_L[l].kp, h_L[l].kp / 64, wm, st, mx, 0);
    };
    auto gsm = [&](int l, const float* Hin, const float* mn, const float* rs,
                   const float* bias, float* Hout, int wm, int st, int mx, int ib) {
        dim3 grid(BN_TOT / 256, h_L[l].rows / 128, 1);
        kan_mma<2, 8, 256><<<grid, 512, SMEM_TILE>>>(Hin, mn, rs,
            whi + h_L[l].woff, wlo + h_L[l].woff, bias, Hout, ps, pqb, pm,
            h_L[l].cin, h_L[l].cout, h_L[l].kp, h_L[l].kp / 64, wm, st, mx, ib);
    };
    auto fin = [&](int slot, int C, int gx) {
        bn_fin<<<(C + 7) / 8, 256>>>(ps, pqb, M(slot), R(slot), C, gx);
    };

    gsm(0, x, nullptr, nullptr, nullptr, h1, 0, 1, 0, 1);   fin(0, 64, 128);
    gsm(1, h1, M(0), R(0), nullptr, h2, 0, 1, 0, 0);        fin(1, 64, 128);
    gsm(2, h2, M(1), R(1), nullptr, h3, 0, 1, 0, 0);        fin(2, 64, 128);
    gsm(3, h3, M(2), R(2), nullptr, h4, 0, 1, 0, 0);        fin(3, 128, 128);
    gbig(4, h4, M(3), R(3), nullptr, nullptr, 2, 1, 1);     fin(4, 1024, 256);

    {
        dim3 g(2, BB);
        gfbias6<<<g, 256>>>(pm, M(4), R(4), wp.p[5], bias6);
    }

    gbig(5, h2, M(1), R(1), bias6, h6, 0, 1, 0);            fin(5, 512, 256);
    gbig(6, h6, M(5), R(5), nullptr, h7, 0, 1, 0);          fin(6, 256, 256);
    gsm(7, h7, M(6), R(6), nullptr, h8, 0, 1, 0, 0);        fin(7, 128, 128);
    gsm(8, h8, M(7), R(7), nullptr, h9, 0, 1, 0, 0);        fin(8, 128, 128);
    gsm(9, h9, M(8), R(8), nullptr, (float*)d_out, 1, 0, 0, 0);
}